// round 12
// baseline (speedup 1.0000x reference)
#include <cuda_runtime.h>
#include <float.h>
#include <math.h>

// Problem constants (fixed shapes from reference setup_inputs)
#define D_DIM   2048
#define SK      64       // sqrt_K
#define NEXPERT 4096     // SK*SK
#define TOPK    8
#define NMAX    8192

typedef unsigned long long ULL;

// Scratch for fused projection S = x @ [W1;W2]^T  -> [N, 128]
__device__ float g_S[NMAX * 2 * SK];

// ---------------------------------------------------------------------------
// packed f32x2 helpers (exact fp32)
// ---------------------------------------------------------------------------
__device__ __forceinline__ ULL pk2(float lo, float hi) {
    ULL r;
    asm("mov.b64 %0, {%1, %2};" : "=l"(r) : "f"(lo), "f"(hi));
    return r;
}
__device__ __forceinline__ void fma2(ULL& d, ULL a, ULL b) {
    asm("fma.rn.f32x2 %0, %1, %2, %0;" : "+l"(d) : "l"(a), "l"(b));
}

// ---------------------------------------------------------------------------
// Kernel A: SGEMM  S[N,128] = x[N,2048] @ concat(W1,W2)[128,2048]^T
// Occupancy-targeted: BM=32 (warp = 4 rows x 128 cols), 256 thr, grid=256
// -> 2048 warps chip-wide (~3.4/SMSP) vs 1024 before.  Inner loop per kk:
// 1 broadcast LDS.128 (A) + 1 LDS.128 (B) + 4 pk2 + 8 fma2.
// Per-(row,col) accumulation sequential over k — bit-identical numerics.
// ---------------------------------------------------------------------------
#define BM 32
#define BN 128
#define BK 16
#define NIT (D_DIM / BK)

__global__ __launch_bounds__(256, 2) void pkr_gemm(
    const float* __restrict__ x,
    const float* __restrict__ W1,
    const float* __restrict__ W2)
{
    __shared__ float As[2][BK][BM];   // 2 x 2 KB
    __shared__ float Bs[2][BK][BN];   // 2 x 8 KB

    const int tid  = threadIdx.x;
    const int w    = tid >> 5;
    const int lane = tid & 31;
    const int bm0  = blockIdx.x * BM;

    // A loader: threads 0..127; row ar (0..31), k offset akc in {0,4,8,12}
    const bool a_on = (tid < 128);
    const int ar  = tid >> 2;            // valid when a_on
    const int akc = (tid & 3) * 4;
    const float* xp = x + (size_t)(bm0 + (a_on ? ar : 0)) * D_DIM + akc;

    // B loader (R2-identical): col bc (0..63), k offset bkc in {0,4,8,12}
    const int bc  = tid & 63;
    const int bkc = (tid >> 6) * 4;
    const float* w1p = W1 + (size_t)bc * D_DIM + bkc;
    const float* w2p = W2 + (size_t)bc * D_DIM + bkc;

    ULL acc[4][2];
    #pragma unroll
    for (int i = 0; i < 4; i++) { acc[i][0] = 0ULL; acc[i][1] = 0ULL; }

    // stage 0 fill
    {
        if (a_on) {
            float4 a = *(const float4*)xp;
            As[0][akc + 0][ar] = a.x;  As[0][akc + 1][ar] = a.y;
            As[0][akc + 2][ar] = a.z;  As[0][akc + 3][ar] = a.w;
        }
        float4 b1 = *(const float4*)w1p;
        float4 b2 = *(const float4*)w2p;
        Bs[0][bkc + 0][bc] = b1.x; Bs[0][bkc + 1][bc] = b1.y;
        Bs[0][bkc + 2][bc] = b1.z; Bs[0][bkc + 3][bc] = b1.w;
        Bs[0][bkc + 0][bc + SK] = b2.x; Bs[0][bkc + 1][bc + SK] = b2.y;
        Bs[0][bkc + 2][bc + SK] = b2.z; Bs[0][bkc + 3][bc + SK] = b2.w;
    }
    __syncthreads();

    int p = 0;
    float4 a_pf, b1_pf, b2_pf;
    for (int it = 0; it < NIT; ++it) {
        const bool has_next = (it + 1) < NIT;
        if (has_next) {
            const int k0 = (it + 1) * BK;
            if (a_on) a_pf = *(const float4*)(xp + k0);
            b1_pf = *(const float4*)(w1p + k0);
            b2_pf = *(const float4*)(w2p + k0);
        }

        #pragma unroll
        for (int kk = 0; kk < BK; kk++) {
            float4 a4 = *(const float4*)&As[p][kk][w * 4];      // broadcast
            ulonglong2 bb = *(const ulonglong2*)&Bs[p][kk][lane * 4];
            ULL a0 = pk2(a4.x, a4.x), a1 = pk2(a4.y, a4.y);
            ULL a2 = pk2(a4.z, a4.z), a3 = pk2(a4.w, a4.w);
            fma2(acc[0][0], a0, bb.x); fma2(acc[0][1], a0, bb.y);
            fma2(acc[1][0], a1, bb.x); fma2(acc[1][1], a1, bb.y);
            fma2(acc[2][0], a2, bb.x); fma2(acc[2][1], a2, bb.y);
            fma2(acc[3][0], a3, bb.x); fma2(acc[3][1], a3, bb.y);
        }

        if (has_next) {
            const int q = p ^ 1;
            if (a_on) {
                As[q][akc + 0][ar] = a_pf.x;  As[q][akc + 1][ar] = a_pf.y;
                As[q][akc + 2][ar] = a_pf.z;  As[q][akc + 3][ar] = a_pf.w;
            }
            Bs[q][bkc + 0][bc] = b1_pf.x; Bs[q][bkc + 1][bc] = b1_pf.y;
            Bs[q][bkc + 2][bc] = b1_pf.z; Bs[q][bkc + 3][bc] = b1_pf.w;
            Bs[q][bkc + 0][bc + SK] = b2_pf.x; Bs[q][bkc + 1][bc + SK] = b2_pf.y;
            Bs[q][bkc + 2][bc + SK] = b2_pf.z; Bs[q][bkc + 3][bc + SK] = b2_pf.w;
            __syncthreads();
            p = q;
        }
    }

    #pragma unroll
    for (int i = 0; i < 4; i++) {
        const size_t row = (size_t)(bm0 + w * 4 + i);
        ulonglong2 v; v.x = acc[i][0]; v.y = acc[i][1];
        *(ulonglong2*)&g_S[row * (2 * SK) + lane * 4] = v;
    }
}

// ---------------------------------------------------------------------------
// Kernel B (R9 verbatim, measured 24.7us): one warp per row; score stream
// interleaved into the s1/s2 argmax rounds; stable tie-breaks everywhere.
// ---------------------------------------------------------------------------
__global__ __launch_bounds__(256) void pkr_topk(
    float* __restrict__ idx_out,
    float* __restrict__ probs_out,
    float* __restrict__ scores_out)
{
    __shared__ float sb[8][2 * SK];
    __shared__ float c1v[8][8], c2v[8][8];
    __shared__ int   c1i[8][8], c2i[8][8];

    const int w    = threadIdx.x >> 5;
    const int lane = threadIdx.x & 31;
    const size_t row = (size_t)blockIdx.x * 8 + w;

    *(float4*)&sb[w][lane * 4] =
        *(const float4*)&g_S[row * (2 * SK) + lane * 4];
    __syncwarp();

    float* __restrict__ srow =
        scores_out ? scores_out + row * NEXPERT : (float*)0;
    const int j = (lane & 15) * 4;
    const float4 s2q = *(const float4*)&sb[w][SK + j];
    const int ihalf = lane >> 4;

    float a0 = sb[w][lane],      a1 = sb[w][lane + 32];
    int   i0 = lane,             i1 = lane + 32;
    float b0 = sb[w][SK + lane], b1 = sb[w][SK + lane + 32];
    int   j0 = lane,             j1 = lane + 32;

    #pragma unroll
    for (int r = 0; r < TOPK; r++) {
        if (srow) {
            #pragma unroll
            for (int u = 0; u < 4; u++) {
                const int t = r * 4 + u;
                const int i = t * 2 + ihalf;
                const float s1 = sb[w][i];
                float4 v4;
                v4.x = s1 + s2q.x; v4.y = s1 + s2q.y;
                v4.z = s1 + s2q.z; v4.w = s1 + s2q.w;
                __stcs((float4*)&srow[i * SK + j], v4);
            }
        }
        {
            float v; int i;
            if (a0 > a1 || (a0 == a1 && i0 < i1)) { v = a0; i = i0; }
            else                                  { v = a1; i = i1; }
            #pragma unroll
            for (int off = 16; off; off >>= 1) {
                float ov = __shfl_xor_sync(0xffffffffu, v, off);
                int   oi = __shfl_xor_sync(0xffffffffu, i, off);
                if (ov > v || (ov == v && oi < i)) { v = ov; i = oi; }
            }
            if (lane == r) { c1v[w][r] = v; c1i[w][r] = i; }
            if (i == i0) { a0 = -FLT_MAX; i0 = 1 << 30; }
            if (i == i1) { a1 = -FLT_MAX; i1 = 1 << 30; }
        }
        {
            float u; int jj;
            if (b0 > b1 || (b0 == b1 && j0 < j1)) { u = b0; jj = j0; }
            else                                  { u = b1; jj = j1; }
            #pragma unroll
            for (int off = 16; off; off >>= 1) {
                float ou = __shfl_xor_sync(0xffffffffu, u, off);
                int   oj = __shfl_xor_sync(0xffffffffu, jj, off);
                if (ou > u || (ou == u && oj < jj)) { u = ou; jj = oj; }
            }
            if (lane == r) { c2v[w][r] = u; c2i[w][r] = jj; }
            if (jj == j0) { b0 = -FLT_MAX; j0 = 1 << 30; }
            if (jj == j1) { b1 = -FLT_MAX; j1 = 1 << 30; }
        }
    }
    __syncwarp();

    const int p0 = lane, p1 = lane + 32;
    float cv0 = c1v[w][p0 >> 3] + c2v[w][p0 & 7];
    int   ci0 = c1i[w][p0 >> 3] * SK + c2i[w][p0 & 7];
    float cv1 = c1v[w][p1 >> 3] + c2v[w][p1 & 7];
    int   ci1 = c1i[w][p1 >> 3] * SK + c2i[w][p1 & 7];

    float mv[TOPK];
    int   mi[TOPK];
    #pragma unroll
    for (int r = 0; r < TOPK; r++) {
        float v; int i;
        if (cv0 > cv1 || (cv0 == cv1 && ci0 < ci1)) { v = cv0; i = ci0; }
        else                                        { v = cv1; i = ci1; }
        #pragma unroll
        for (int off = 16; off; off >>= 1) {
            float ov = __shfl_xor_sync(0xffffffffu, v, off);
            int   oi = __shfl_xor_sync(0xffffffffu, i, off);
            if (ov > v || (ov == v && oi < i)) { v = ov; i = oi; }
        }
        mv[r] = v; mi[r] = i;
        if (i == ci0) { cv0 = -FLT_MAX; ci0 = 1 << 30; }
        if (i == ci1) { cv1 = -FLT_MAX; ci1 = 1 << 30; }
    }

    if (lane == 0) {
        float m = mv[0], sum = 0.f, e[TOPK];
        #pragma unroll
        for (int r = 0; r < TOPK; r++) { e[r] = expf(mv[r] - m); sum += e[r]; }
        float inv = 1.f / sum;
        #pragma unroll
        for (int r = 0; r < TOPK; r++) {
            if (idx_out)   idx_out[row * TOPK + r]   = (float)mi[r];
            if (probs_out) probs_out[row * TOPK + r] = e[r] * inv;
        }
    }
}

// ---------------------------------------------------------------------------
extern "C" void kernel_launch(void* const* d_in, const int* in_sizes, int n_in,
                              void* d_out, int out_size) {
    const float* x  = (const float*)d_in[0];
    const float* W1 = (const float*)d_in[1];
    const float* W2 = (const float*)d_in[2];
    (void)n_in;

    int N = in_sizes[0] / D_DIM;   // 8192
    float* out = (float*)d_out;

    float* idxp = 0;
    float* probp = 0;
    float* scorep = 0;
    long long full = (long long)N * (2 * TOPK + NEXPERT);
    if ((long long)out_size == full) {
        idxp   = out;
        probp  = out + (long long)N * TOPK;
        scorep = out + (long long)N * 2 * TOPK;
    } else if ((long long)out_size == (long long)N * NEXPERT) {
        scorep = out;
    } else if ((long long)out_size == (long long)N * 2 * TOPK) {
        idxp  = out;
        probp = out + (long long)N * TOPK;
    } else {
        idxp   = out;
        probp  = out + (long long)N * TOPK;
        scorep = out + (long long)N * 2 * TOPK;
    }

    pkr_gemm<<<N / BM, 256>>>(x, W1, W2);
    pkr_topk<<<N / 8, 256>>>(idxp, probp, scorep);
}

// round 13
// speedup vs baseline: 1.3177x; 1.3177x over previous
#include <cuda_runtime.h>
#include <float.h>
#include <math.h>

// Problem constants (fixed shapes from reference setup_inputs)
#define D_DIM   2048
#define SK      64       // sqrt_K
#define NEXPERT 4096     // SK*SK
#define TOPK    8
#define NMAX    8192

typedef unsigned long long ULL;

// Scratch for fused projection S = x @ [W1;W2]^T  -> [N, 128]
__device__ float g_S[NMAX * 2 * SK];

// ---------------------------------------------------------------------------
// packed f32x2 helpers (exact fp32)
// ---------------------------------------------------------------------------
__device__ __forceinline__ ULL pk2(float lo, float hi) {
    ULL r;
    asm("mov.b64 %0, {%1, %2};" : "=l"(r) : "f"(lo), "f"(hi));
    return r;
}
__device__ __forceinline__ void fma2(ULL& d, ULL a, ULL b) {
    asm("fma.rn.f32x2 %0, %1, %2, %0;" : "+l"(d) : "l"(a), "l"(b));
}

// ---------------------------------------------------------------------------
// Kernel A: SGEMM  S[N,128] = x[N,2048] @ concat(W1,W2)[128,2048]^T
// Classic SIMT tile: CTA 64x128, 128 threads (4 warps of 32x64),
// thread tile 8x8.  Per kk: 4 LDS.128 + 8 pk2 + 32 fma2 (ILP 32).
// Per-(row,col) accumulation sequential over k — bit-identical numerics.
// ---------------------------------------------------------------------------
#define BM  64
#define BN  128
#define BK  16
#define NIT (D_DIM / BK)
#define ASTR 68     // As row stride in floats (16B-aligned, de-conflicted)
#define BSTR 132    // Bs row stride in floats

__global__ __launch_bounds__(128) void pkr_gemm(
    const float* __restrict__ x,
    const float* __restrict__ W1,
    const float* __restrict__ W2)
{
    __shared__ float As[2][BK * ASTR];   // 2 x 4352 B
    __shared__ float Bs[2][BK * BSTR];   // 2 x 8448 B

    const int tid  = threadIdx.x;
    const int warp = tid >> 5;
    const int lane = tid & 31;
    const int bm0  = blockIdx.x * BM;

    // warp tile origin, thread-in-warp mapping (4 row-groups x 8 col-groups)
    const int wr0  = (warp & 1) * 32;
    const int wc0  = (warp >> 1) * 64;
    const int rowg = lane >> 3;          // 0..3
    const int colg = lane & 7;           // 0..7
    const int r0   = wr0 + rowg * 8;     // thread's first row in tile
    const int c0   = wc0 + colg * 8;     // thread's first col in tile

    // A loader: 2 jobs; row arow(m) = (tid>>2)+m*32, k-quad akc = (tid&3)*4
    const int arbase = tid >> 2;         // 0..31
    const int akc    = (tid & 3) * 4;
    const float* xp0 = x + (size_t)(bm0 + arbase)      * D_DIM + akc;
    const float* xp1 = x + (size_t)(bm0 + arbase + 32) * D_DIM + akc;

    // B loader: 4 jobs; brow(m) = (tid>>2)+m*32 (0..127), same k-quad
    const float* wp[4];
    wp[0] = W1 + (size_t)(arbase)      * D_DIM + akc;
    wp[1] = W1 + (size_t)(arbase + 32) * D_DIM + akc;
    wp[2] = W2 + (size_t)(arbase)      * D_DIM + akc;
    wp[3] = W2 + (size_t)(arbase + 32) * D_DIM + akc;

    ULL acc[8][4];
    #pragma unroll
    for (int i = 0; i < 8; i++)
        #pragma unroll
        for (int j = 0; j < 4; j++) acc[i][j] = 0ULL;

    // ---- stage 0 fill ----
    {
        float4 a0 = *(const float4*)xp0;
        float4 a1 = *(const float4*)xp1;
        #pragma unroll
        for (int i = 0; i < 4; i++) {
            As[0][(akc + i) * 1 + 0] = 0.f;   // (dummy to keep shape; overwritten)
        }
        #pragma unroll
        for (int i = 0; i < 4; i++) {
            As[0][(akc + i) * ASTR + arbase]      = ((const float*)&a0)[i];
            As[0][(akc + i) * ASTR + arbase + 32] = ((const float*)&a1)[i];
        }
        #pragma unroll
        for (int m = 0; m < 4; m++) {
            float4 b = *(const float4*)wp[m];
            const int brow = arbase + (m & 1) * 32 + (m >> 1) * 64;
            #pragma unroll
            for (int i = 0; i < 4; i++)
                Bs[0][(akc + i) * BSTR + brow] = ((const float*)&b)[i];
        }
    }
    __syncthreads();

    int p = 0;
    float4 a0_pf, a1_pf, b_pf[4];
    for (int it = 0; it < NIT; ++it) {
        const bool has_next = (it + 1) < NIT;
        if (has_next) {
            const int k0 = (it + 1) * BK;
            a0_pf = *(const float4*)(xp0 + k0);
            a1_pf = *(const float4*)(xp1 + k0);
            #pragma unroll
            for (int m = 0; m < 4; m++)
                b_pf[m] = *(const float4*)(wp[m] + k0);
        }

        const float* Ap = As[p];
        const float* Bp = Bs[p];
        #pragma unroll
        for (int kk = 0; kk < BK; kk++) {
            float4 af0 = *(const float4*)&Ap[kk * ASTR + r0];
            float4 af1 = *(const float4*)&Ap[kk * ASTR + r0 + 4];
            ulonglong2 bf0 = *(const ulonglong2*)&Bp[kk * BSTR + c0];
            ulonglong2 bf1 = *(const ulonglong2*)&Bp[kk * BSTR + c0 + 4];
            float av[8] = {af0.x, af0.y, af0.z, af0.w,
                           af1.x, af1.y, af1.z, af1.w};
            #pragma unroll
            for (int i = 0; i < 8; i++) {
                ULL ad = pk2(av[i], av[i]);
                fma2(acc[i][0], ad, bf0.x);
                fma2(acc[i][1], ad, bf0.y);
                fma2(acc[i][2], ad, bf1.x);
                fma2(acc[i][3], ad, bf1.y);
            }
        }

        if (has_next) {
            const int q = p ^ 1;
            #pragma unroll
            for (int i = 0; i < 4; i++) {
                As[q][(akc + i) * ASTR + arbase]      = ((const float*)&a0_pf)[i];
                As[q][(akc + i) * ASTR + arbase + 32] = ((const float*)&a1_pf)[i];
            }
            #pragma unroll
            for (int m = 0; m < 4; m++) {
                const int brow = arbase + (m & 1) * 32 + (m >> 1) * 64;
                #pragma unroll
                for (int i = 0; i < 4; i++)
                    Bs[q][(akc + i) * BSTR + brow] = ((const float*)&b_pf[m])[i];
            }
            __syncthreads();
            p = q;
        }
    }

    // ---- epilogue: acc[i][j] = cols (c0+2j, c0+2j+1) of row r0+i ----
    #pragma unroll
    for (int i = 0; i < 8; i++) {
        const size_t row = (size_t)(bm0 + r0 + i);
        ulonglong2 v0; v0.x = acc[i][0]; v0.y = acc[i][1];
        ulonglong2 v1; v1.x = acc[i][2]; v1.y = acc[i][3];
        *(ulonglong2*)&g_S[row * BN + c0]     = v0;
        *(ulonglong2*)&g_S[row * BN + c0 + 4] = v1;
    }
}

// ---------------------------------------------------------------------------
// Kernel B (R9 verbatim, measured 24.7us): one warp per row; score stream
// interleaved into the s1/s2 argmax rounds; stable tie-breaks everywhere.
// ---------------------------------------------------------------------------
__global__ __launch_bounds__(256) void pkr_topk(
    float* __restrict__ idx_out,
    float* __restrict__ probs_out,
    float* __restrict__ scores_out)
{
    __shared__ float sb[8][2 * SK];
    __shared__ float c1v[8][8], c2v[8][8];
    __shared__ int   c1i[8][8], c2i[8][8];

    const int w    = threadIdx.x >> 5;
    const int lane = threadIdx.x & 31;
    const size_t row = (size_t)blockIdx.x * 8 + w;

    *(float4*)&sb[w][lane * 4] =
        *(const float4*)&g_S[row * (2 * SK) + lane * 4];
    __syncwarp();

    float* __restrict__ srow =
        scores_out ? scores_out + row * NEXPERT : (float*)0;
    const int j = (lane & 15) * 4;
    const float4 s2q = *(const float4*)&sb[w][SK + j];
    const int ihalf = lane >> 4;

    float a0 = sb[w][lane],      a1 = sb[w][lane + 32];
    int   i0 = lane,             i1 = lane + 32;
    float b0 = sb[w][SK + lane], b1 = sb[w][SK + lane + 32];
    int   j0 = lane,             j1 = lane + 32;

    #pragma unroll
    for (int r = 0; r < TOPK; r++) {
        if (srow) {
            #pragma unroll
            for (int u = 0; u < 4; u++) {
                const int t = r * 4 + u;
                const int i = t * 2 + ihalf;
                const float s1 = sb[w][i];
                float4 v4;
                v4.x = s1 + s2q.x; v4.y = s1 + s2q.y;
                v4.z = s1 + s2q.z; v4.w = s1 + s2q.w;
                __stcs((float4*)&srow[i * SK + j], v4);
            }
        }
        {
            float v; int i;
            if (a0 > a1 || (a0 == a1 && i0 < i1)) { v = a0; i = i0; }
            else                                  { v = a1; i = i1; }
            #pragma unroll
            for (int off = 16; off; off >>= 1) {
                float ov = __shfl_xor_sync(0xffffffffu, v, off);
                int   oi = __shfl_xor_sync(0xffffffffu, i, off);
                if (ov > v || (ov == v && oi < i)) { v = ov; i = oi; }
            }
            if (lane == r) { c1v[w][r] = v; c1i[w][r] = i; }
            if (i == i0) { a0 = -FLT_MAX; i0 = 1 << 30; }
            if (i == i1) { a1 = -FLT_MAX; i1 = 1 << 30; }
        }
        {
            float u; int jj;
            if (b0 > b1 || (b0 == b1 && j0 < j1)) { u = b0; jj = j0; }
            else                                  { u = b1; jj = j1; }
            #pragma unroll
            for (int off = 16; off; off >>= 1) {
                float ou = __shfl_xor_sync(0xffffffffu, u, off);
                int   oj = __shfl_xor_sync(0xffffffffu, jj, off);
                if (ou > u || (ou == u && oj < jj)) { u = ou; jj = oj; }
            }
            if (lane == r) { c2v[w][r] = u; c2i[w][r] = jj; }
            if (jj == j0) { b0 = -FLT_MAX; j0 = 1 << 30; }
            if (jj == j1) { b1 = -FLT_MAX; j1 = 1 << 30; }
        }
    }
    __syncwarp();

    const int p0 = lane, p1 = lane + 32;
    float cv0 = c1v[w][p0 >> 3] + c2v[w][p0 & 7];
    int   ci0 = c1i[w][p0 >> 3] * SK + c2i[w][p0 & 7];
    float cv1 = c1v[w][p1 >> 3] + c2v[w][p1 & 7];
    int   ci1 = c1i[w][p1 >> 3] * SK + c2i[w][p1 & 7];

    float mv[TOPK];
    int   mi[TOPK];
    #pragma unroll
    for (int r = 0; r < TOPK; r++) {
        float v; int i;
        if (cv0 > cv1 || (cv0 == cv1 && ci0 < ci1)) { v = cv0; i = ci0; }
        else                                        { v = cv1; i = ci1; }
        #pragma unroll
        for (int off = 16; off; off >>= 1) {
            float ov = __shfl_xor_sync(0xffffffffu, v, off);
            int   oi = __shfl_xor_sync(0xffffffffu, i, off);
            if (ov > v || (ov == v && oi < i)) { v = ov; i = oi; }
        }
        mv[r] = v; mi[r] = i;
        if (i == ci0) { cv0 = -FLT_MAX; ci0 = 1 << 30; }
        if (i == ci1) { cv1 = -FLT_MAX; ci1 = 1 << 30; }
    }

    if (lane == 0) {
        float m = mv[0], sum = 0.f, e[TOPK];
        #pragma unroll
        for (int r = 0; r < TOPK; r++) { e[r] = expf(mv[r] - m); sum += e[r]; }
        float inv = 1.f / sum;
        #pragma unroll
        for (int r = 0; r < TOPK; r++) {
            if (idx_out)   idx_out[row * TOPK + r]   = (float)mi[r];
            if (probs_out) probs_out[row * TOPK + r] = e[r] * inv;
        }
    }
}

// ---------------------------------------------------------------------------
extern "C" void kernel_launch(void* const* d_in, const int* in_sizes, int n_in,
                              void* d_out, int out_size) {
    const float* x  = (const float*)d_in[0];
    const float* W1 = (const float*)d_in[1];
    const float* W2 = (const float*)d_in[2];
    (void)n_in;

    int N = in_sizes[0] / D_DIM;   // 8192
    float* out = (float*)d_out;

    float* idxp = 0;
    float* probp = 0;
    float* scorep = 0;
    long long full = (long long)N * (2 * TOPK + NEXPERT);
    if ((long long)out_size == full) {
        idxp   = out;
        probp  = out + (long long)N * TOPK;
        scorep = out + (long long)N * 2 * TOPK;
    } else if ((long long)out_size == (long long)N * NEXPERT) {
        scorep = out;
    } else if ((long long)out_size == (long long)N * 2 * TOPK) {
        idxp  = out;
        probp = out + (long long)N * TOPK;
    } else {
        idxp   = out;
        probp  = out + (long long)N * TOPK;
        scorep = out + (long long)N * 2 * TOPK;
    }

    pkr_gemm<<<N / BM, 128>>>(x, W1, W2);
    pkr_topk<<<N / 8, 256>>>(idxp, probp, scorep);
}

// round 14
// speedup vs baseline: 1.4651x; 1.1118x over previous
#include <cuda_runtime.h>
#include <float.h>
#include <math.h>

// Problem constants (fixed shapes from reference setup_inputs)
#define D_DIM   2048
#define SK      64       // sqrt_K
#define NEXPERT 4096     // SK*SK
#define TOPK    8
#define NMAX    8192

typedef unsigned long long ULL;

// Scratch for fused projection S = x @ [W1;W2]^T  -> [N, 128]
__device__ float g_S[NMAX * 2 * SK];

// ---------------------------------------------------------------------------
// packed f32x2 helpers (exact fp32)
// ---------------------------------------------------------------------------
__device__ __forceinline__ ULL pk2(float lo, float hi) {
    ULL r;
    asm("mov.b64 %0, {%1, %2};" : "=l"(r) : "f"(lo), "f"(hi));
    return r;
}
__device__ __forceinline__ void fma2(ULL& d, ULL a, ULL b) {
    asm("fma.rn.f32x2 %0, %1, %2, %0;" : "+l"(d) : "l"(a), "l"(b));
}

// ---------------------------------------------------------------------------
// Kernel A (R2 verbatim — measured 140us, empirical optimum over 6 variants):
// SGEMM  S[N,128] = x[N,2048] @ concat(W1,W2)[128,2048]^T
// BM=64 x BN=128, BK=16, 256 threads, double-buffered smem.
// ---------------------------------------------------------------------------
#define BM 64
#define BN 128
#define BK 16
#define NIT (D_DIM / BK)

__global__ __launch_bounds__(256) void pkr_gemm(
    const float* __restrict__ x,
    const float* __restrict__ W1,
    const float* __restrict__ W2)
{
    __shared__ float As[2][BK][BM];   // 2 x 4 KB
    __shared__ float Bs[2][BK][BN];   // 2 x 8 KB

    const int tid  = threadIdx.x;
    const int w    = tid >> 5;
    const int lane = tid & 31;
    const int bm0  = blockIdx.x * BM;

    const int ar  = tid >> 2;
    const int akc = (tid & 3) * 4;
    const float* xp = x + (size_t)(bm0 + ar) * D_DIM + akc;

    const int bc  = tid & 63;
    const int bkc = (tid >> 6) * 4;
    const float* w1p = W1 + (size_t)bc * D_DIM + bkc;
    const float* w2p = W2 + (size_t)bc * D_DIM + bkc;

    ULL acc[8][2];
    #pragma unroll
    for (int i = 0; i < 8; i++) { acc[i][0] = 0ULL; acc[i][1] = 0ULL; }

    {
        float4 a  = *(const float4*)xp;
        float4 b1 = *(const float4*)w1p;
        float4 b2 = *(const float4*)w2p;
        As[0][akc + 0][ar] = a.x;  As[0][akc + 1][ar] = a.y;
        As[0][akc + 2][ar] = a.z;  As[0][akc + 3][ar] = a.w;
        Bs[0][bkc + 0][bc] = b1.x; Bs[0][bkc + 1][bc] = b1.y;
        Bs[0][bkc + 2][bc] = b1.z; Bs[0][bkc + 3][bc] = b1.w;
        Bs[0][bkc + 0][bc + SK] = b2.x; Bs[0][bkc + 1][bc + SK] = b2.y;
        Bs[0][bkc + 2][bc + SK] = b2.z; Bs[0][bkc + 3][bc + SK] = b2.w;
    }
    __syncthreads();

    int p = 0;
    float4 a_pf, b1_pf, b2_pf;
    for (int it = 0; it < NIT; ++it) {
        const bool has_next = (it + 1) < NIT;
        if (has_next) {
            const int k0 = (it + 1) * BK;
            a_pf  = *(const float4*)(xp  + k0);
            b1_pf = *(const float4*)(w1p + k0);
            b2_pf = *(const float4*)(w2p + k0);
        }

        #pragma unroll
        for (int kk = 0; kk < BK; kk++) {
            float4 a01 = *(const float4*)&As[p][kk][w * 8];
            float4 a23 = *(const float4*)&As[p][kk][w * 8 + 4];
            ulonglong2 bb = *(const ulonglong2*)&Bs[p][kk][lane * 4];
            float av[8] = {a01.x, a01.y, a01.z, a01.w,
                           a23.x, a23.y, a23.z, a23.w};
            #pragma unroll
            for (int i = 0; i < 8; i++) {
                ULL ad = pk2(av[i], av[i]);
                fma2(acc[i][0], ad, bb.x);
                fma2(acc[i][1], ad, bb.y);
            }
        }

        if (has_next) {
            const int q = p ^ 1;
            As[q][akc + 0][ar] = a_pf.x;  As[q][akc + 1][ar] = a_pf.y;
            As[q][akc + 2][ar] = a_pf.z;  As[q][akc + 3][ar] = a_pf.w;
            Bs[q][bkc + 0][bc] = b1_pf.x; Bs[q][bkc + 1][bc] = b1_pf.y;
            Bs[q][bkc + 2][bc] = b1_pf.z; Bs[q][bkc + 3][bc] = b1_pf.w;
            Bs[q][bkc + 0][bc + SK] = b2_pf.x; Bs[q][bkc + 1][bc + SK] = b2_pf.y;
            Bs[q][bkc + 2][bc + SK] = b2_pf.z; Bs[q][bkc + 3][bc + SK] = b2_pf.w;
            __syncthreads();
            p = q;
        }
    }

    #pragma unroll
    for (int i = 0; i < 8; i++) {
        const size_t row = (size_t)(bm0 + w * 8 + i);
        ulonglong2 v; v.x = acc[i][0]; v.y = acc[i][1];
        *(ulonglong2*)&g_S[row * (2 * SK) + lane * 4] = v;
    }
}

// ---------------------------------------------------------------------------
// Kernel B v3: TWO warps per row (grid N/4, 256 thr).
//   half 0: streams score rows i in [0,32)  + computes s1 top-8
//   half 1: streams score rows i in [32,64) + computes s2 top-8
// then __syncthreads and half-0 warps merge 64 candidates -> top-8 -> softmax.
// Identical arithmetic + stable tie-breaks as the passing R9 kernel.
// ---------------------------------------------------------------------------
__global__ __launch_bounds__(256) void pkr_topk(
    float* __restrict__ idx_out,
    float* __restrict__ probs_out,
    float* __restrict__ scores_out)
{
    __shared__ float sb[4][2 * SK];
    __shared__ float c1v[4][8], c2v[4][8];
    __shared__ int   c1i[4][8], c2i[4][8];

    const int tid  = threadIdx.x;
    const int warp = tid >> 5;
    const int lane = tid & 31;
    const int rl   = warp >> 1;      // row-in-block 0..3
    const int half = warp & 1;       // 0: s1 side, 1: s2 side
    const size_t row = (size_t)blockIdx.x * 4 + rl;

    // block loads 4 rows x 128 floats = 128 float4 (first 128 threads)
    if (tid < 128) {
        ((float4*)sb)[tid] = ((const float4*)g_S)[blockIdx.x * 128 + tid];
    }
    __syncthreads();

    // --- stream setup: this warp covers i in [half*32, half*32+32) ---
    float* __restrict__ srow =
        scores_out ? scores_out + row * NEXPERT : (float*)0;
    const int j = (lane & 15) * 4;
    const float4 s2q = *(const float4*)&sb[rl][SK + j];
    const int ihalf = lane >> 4;
    const int ibase = half * 32;

    // --- this warp's top-8 source: s1 (half 0) or s2 (half 1) ---
    const int sbase = half * SK;
    float a0 = sb[rl][sbase + lane], a1 = sb[rl][sbase + lane + 32];
    int   i0 = lane,                 i1 = lane + 32;

    #pragma unroll
    for (int r = 0; r < TOPK; r++) {
        // 2 interleaved stream iterations per round (16 total per warp)
        if (srow) {
            #pragma unroll
            for (int u = 0; u < 2; u++) {
                const int t = r * 2 + u;
                const int i = ibase + t * 2 + ihalf;
                const float s1 = sb[rl][i];
                float4 v4;
                v4.x = s1 + s2q.x; v4.y = s1 + s2q.y;
                v4.z = s1 + s2q.z; v4.w = s1 + s2q.w;
                __stcs((float4*)&srow[i * SK + j], v4);
            }
        }
        // argmax round r over this warp's 64 values
        {
            float v; int i;
            if (a0 > a1 || (a0 == a1 && i0 < i1)) { v = a0; i = i0; }
            else                                  { v = a1; i = i1; }
            #pragma unroll
            for (int off = 16; off; off >>= 1) {
                float ov = __shfl_xor_sync(0xffffffffu, v, off);
                int   oi = __shfl_xor_sync(0xffffffffu, i, off);
                if (ov > v || (ov == v && oi < i)) { v = ov; i = oi; }
            }
            if (lane == r) {
                if (half == 0) { c1v[rl][r] = v; c1i[rl][r] = i; }
                else           { c2v[rl][r] = v; c2i[rl][r] = i; }
            }
            if (i == i0) { a0 = -FLT_MAX; i0 = 1 << 30; }
            if (i == i1) { a1 = -FLT_MAX; i1 = 1 << 30; }
        }
    }
    __syncthreads();

    // --- half-0 warps: top-8 of the 64 candidate pairs (2 per lane) ---
    if (half == 0) {
        const int p0 = lane, p1 = lane + 32;
        float cv0 = c1v[rl][p0 >> 3] + c2v[rl][p0 & 7];
        int   ci0 = c1i[rl][p0 >> 3] * SK + c2i[rl][p0 & 7];
        float cv1 = c1v[rl][p1 >> 3] + c2v[rl][p1 & 7];
        int   ci1 = c1i[rl][p1 >> 3] * SK + c2i[rl][p1 & 7];

        float mv[TOPK];
        int   mi[TOPK];
        #pragma unroll
        for (int r = 0; r < TOPK; r++) {
            float v; int i;
            if (cv0 > cv1 || (cv0 == cv1 && ci0 < ci1)) { v = cv0; i = ci0; }
            else                                        { v = cv1; i = ci1; }
            #pragma unroll
            for (int off = 16; off; off >>= 1) {
                float ov = __shfl_xor_sync(0xffffffffu, v, off);
                int   oi = __shfl_xor_sync(0xffffffffu, i, off);
                if (ov > v || (ov == v && oi < i)) { v = ov; i = oi; }
            }
            mv[r] = v; mi[r] = i;
            if (i == ci0) { cv0 = -FLT_MAX; ci0 = 1 << 30; }
            if (i == ci1) { cv1 = -FLT_MAX; ci1 = 1 << 30; }
        }

        if (lane == 0) {
            float m = mv[0], sum = 0.f, e[TOPK];
            #pragma unroll
            for (int r = 0; r < TOPK; r++) { e[r] = expf(mv[r] - m); sum += e[r]; }
            float inv = 1.f / sum;
            #pragma unroll
            for (int r = 0; r < TOPK; r++) {
                if (idx_out)   idx_out[row * TOPK + r]   = (float)mi[r];
                if (probs_out) probs_out[row * TOPK + r] = e[r] * inv;
            }
        }
    }
}

// ---------------------------------------------------------------------------
extern "C" void kernel_launch(void* const* d_in, const int* in_sizes, int n_in,
                              void* d_out, int out_size) {
    const float* x  = (const float*)d_in[0];
    const float* W1 = (const float*)d_in[1];
    const float* W2 = (const float*)d_in[2];
    (void)n_in;

    int N = in_sizes[0] / D_DIM;   // 8192
    float* out = (float*)d_out;

    float* idxp = 0;
    float* probp = 0;
    float* scorep = 0;
    long long full = (long long)N * (2 * TOPK + NEXPERT);
    if ((long long)out_size == full) {
        idxp   = out;
        probp  = out + (long long)N * TOPK;
        scorep = out + (long long)N * 2 * TOPK;
    } else if ((long long)out_size == (long long)N * NEXPERT) {
        scorep = out;
    } else if ((long long)out_size == (long long)N * 2 * TOPK) {
        idxp  = out;
        probp = out + (long long)N * TOPK;
    } else {
        idxp   = out;
        probp  = out + (long long)N * TOPK;
        scorep = out + (long long)N * 2 * TOPK;
    }

    pkr_gemm<<<N / BM, 256>>>(x, W1, W2);
    pkr_topk<<<N / 4, 256>>>(idxp, probp, scorep);
}